// round 5
// baseline (speedup 1.0000x reference)
#include <cuda_runtime.h>
#include <cuda_bf16.h>
#include <mma.h>
#include <math_constants.h>

#define NPTS 4096
#define DDATA 1024
#define DLAT 64
#define NEDGE (NPTS - 1)
#define ROUNDS 12

using namespace nvcuda;

// ---- scratch (no allocations allowed: device globals) ----
static __device__ float g_ddist[(size_t)NPTS * NPTS];
static __device__ float g_ldist[(size_t)NPTS * NPTS];
static __device__ __nv_bfloat16 g_a16[(size_t)NPTS * (3 * DDATA)];   // [hi|lo|hi]
static __device__ __nv_bfloat16 g_b16[(size_t)NPTS * (3 * DDATA)];   // [hi|hi|lo]
static __device__ __nv_bfloat16 g_al16[(size_t)NPTS * (3 * DLAT)];
static __device__ __nv_bfloat16 g_bl16[(size_t)NPTS * (3 * DLAT)];
static __device__ float g_sqd[NPTS];
static __device__ float g_sql[NPTS];
static __device__ float g_ae[NPTS];
static __device__ int   g_edges[2][NEDGE * 2];
static __device__ int   g_ecnt[2];
static __device__ int   g_done[2];
static __device__ int   g_comp[2][NPTS];
static __device__ int   g_parent[2][NPTS];
static __device__ unsigned long long g_nbest[2][NPTS];
static __device__ unsigned g_dmax_bits;
static __device__ float g_topo;

__global__ void init_kernel() {
    int i = blockIdx.x * blockDim.x + threadIdx.x;
    if (i < NPTS) { g_comp[0][i] = i; g_comp[1][i] = i; }
    if (i == 0) {
        g_dmax_bits = 0u;
        g_ecnt[0] = 0; g_ecnt[1] = 0;
        g_done[0] = 0; g_done[1] = 0;
    }
}

// ---- AE loss + squared norms of y_true (one block per row) ----
__global__ void __launch_bounds__(256) ae_sq_kernel(
    const float* __restrict__ yt, const float* __restrict__ yp) {
    int row = blockIdx.x, tid = threadIdx.x;
    float4 a = ((const float4*)(yt + (size_t)row * DDATA))[tid];
    float4 b = ((const float4*)(yp + (size_t)row * DDATA))[tid];
    float dx = a.x - b.x, dy = a.y - b.y, dz = a.z - b.z, dw = a.w - b.w;
    float ae = dx * dx + dy * dy + dz * dz + dw * dw;
    float sq = a.x * a.x + a.y * a.y + a.z * a.z + a.w * a.w;
#pragma unroll
    for (int off = 16; off; off >>= 1) {
        ae += __shfl_down_sync(0xffffffffu, ae, off);
        sq += __shfl_down_sync(0xffffffffu, sq, off);
    }
    __shared__ float sae[8], ssq[8];
    if ((tid & 31) == 0) { sae[tid >> 5] = ae; ssq[tid >> 5] = sq; }
    __syncthreads();
    if (tid < 8) {
        ae = sae[tid]; sq = ssq[tid];
#pragma unroll
        for (int off = 4; off; off >>= 1) {
            ae += __shfl_down_sync(0xffu, ae, off);
            sq += __shfl_down_sync(0xffu, sq, off);
        }
        if (tid == 0) { g_ae[row] = ae * (1.0f / DDATA); g_sqd[row] = sq; }
    }
}

// ---- squared norms of latent rows (one warp per row) ----
__global__ void __launch_bounds__(32) sq_lat_kernel(const float* __restrict__ lat) {
    int row = blockIdx.x, tid = threadIdx.x;
    float2 v = ((const float2*)(lat + (size_t)row * DLAT))[tid];
    float s = v.x * v.x + v.y * v.y;
#pragma unroll
    for (int off = 16; off; off >>= 1) s += __shfl_down_sync(0xffffffffu, s, off);
    if (tid == 0) g_sql[row] = s;
}

// ---- split fp32 -> [hi|lo|hi] / [hi|hi|lo] bf16 arrays ----
// SHIFT = log2(K/4); each thread handles one float4, writes 6x 8B (bf16x4).
template<int K, int SHIFT>
__global__ void __launch_bounds__(256) split_kernel(
    const float* __restrict__ X, __nv_bfloat16* __restrict__ A,
    __nv_bfloat16* __restrict__ B) {
    int idx = blockIdx.x * blockDim.x + threadIdx.x;
    int i = idx >> SHIFT;
    int kk = (idx & ((1 << SHIFT) - 1)) << 2;
    float4 x = *(const float4*)(X + (size_t)i * K + kk);
    __nv_bfloat162 hi01 = __nv_bfloat162(__float2bfloat16(x.x), __float2bfloat16(x.y));
    __nv_bfloat162 hi23 = __nv_bfloat162(__float2bfloat16(x.z), __float2bfloat16(x.w));
    __nv_bfloat162 lo01 = __nv_bfloat162(
        __float2bfloat16(x.x - __bfloat162float(hi01.x)),
        __float2bfloat16(x.y - __bfloat162float(hi01.y)));
    __nv_bfloat162 lo23 = __nv_bfloat162(
        __float2bfloat16(x.z - __bfloat162float(hi23.x)),
        __float2bfloat16(x.w - __bfloat162float(hi23.y)));
    unsigned long long hi4, lo4;
    ((__nv_bfloat162*)&hi4)[0] = hi01; ((__nv_bfloat162*)&hi4)[1] = hi23;
    ((__nv_bfloat162*)&lo4)[0] = lo01; ((__nv_bfloat162*)&lo4)[1] = lo23;
    size_t base = (size_t)i * (3 * K) + kk;
    *(unsigned long long*)(A + base)         = hi4;
    *(unsigned long long*)(A + base + K)     = lo4;
    *(unsigned long long*)(A + base + 2 * K) = hi4;
    *(unsigned long long*)(B + base)         = hi4;
    *(unsigned long long*)(B + base + K)     = hi4;
    *(unsigned long long*)(B + base + 2 * K) = lo4;
}

// ---- cp.async helpers ----
__device__ __forceinline__ void cp16(unsigned smem, const void* g) {
    asm volatile("cp.async.cg.shared.global [%0], [%1], 16;\n"
                 :: "r"(smem), "l"(g));
}
__device__ __forceinline__ void cp_commit() {
    asm volatile("cp.async.commit_group;\n" ::: "memory");
}
template<int N>
__device__ __forceinline__ void cp_wait() {
    asm volatile("cp.async.wait_group %0;\n" :: "n"(N) : "memory");
}

// ---- tensor-core gram -> Euclidean distance matrix ----
// 128x128 tile, 8 warps (warp tile 32x64), bf16 wmma m16n16k16, KC=32,
// cp.async double-buffered smem. No forced occupancy (avoid spills!).
#define SLD 40   // smem row stride in bf16 elems (80B)
template<int KTOT>
__global__ void __launch_bounds__(256) gram16_kernel(
    const __nv_bfloat16* __restrict__ Ag,
    const __nv_bfloat16* __restrict__ Bg, int which) {
    int bj = blockIdx.x, bi = blockIdx.y;
    if (bi > bj) return;

    __shared__ __nv_bfloat16 As[2][128 * SLD];
    __shared__ __nv_bfloat16 Bs[2][128 * SLD];

    int tid = threadIdx.x;
    int wid = tid >> 5, lane = tid & 31;
    int wm = wid & 3;        // m offset = wm*32
    int wn = wid >> 2;       // n offset = wn*64

    wmma::fragment<wmma::accumulator, 16, 16, 16, float> acc[2][4];
#pragma unroll
    for (int mi = 0; mi < 2; mi++)
#pragma unroll
        for (int ni = 0; ni < 4; ni++) wmma::fill_fragment(acc[mi][ni], 0.0f);

    int row = tid >> 2;                 // 0..63
    int col8 = (tid & 3) << 3;          // 0,8,16,24
    const __nv_bfloat16* Ap = Ag + (size_t)(bi * 128 + row) * KTOT + col8;
    const __nv_bfloat16* Bp = Bg + (size_t)(bj * 128 + row) * KTOT + col8;
    size_t rstride = (size_t)64 * KTOT;

    unsigned sA0 = (unsigned)__cvta_generic_to_shared(&As[0][row * SLD + col8]);
    unsigned sA1 = (unsigned)__cvta_generic_to_shared(&As[0][(row + 64) * SLD + col8]);
    unsigned sB0 = (unsigned)__cvta_generic_to_shared(&Bs[0][row * SLD + col8]);
    unsigned sB1 = (unsigned)__cvta_generic_to_shared(&Bs[0][(row + 64) * SLD + col8]);
    const unsigned stgoff = 128 * SLD * 2;  // bytes per stage

    constexpr int NC = KTOT / 32;
    // preload chunk 0 into stage 0
    cp16(sA0, Ap); cp16(sA1, Ap + rstride);
    cp16(sB0, Bp); cp16(sB1, Bp + rstride);
    cp_commit();

#pragma unroll 1
    for (int c = 0; c < NC; c++) {
        int stage = c & 1;
        if (c + 1 < NC) {
            int nk = (c + 1) * 32;
            unsigned so = (stage ^ 1) * stgoff;
            cp16(sA0 + so, Ap + nk); cp16(sA1 + so, Ap + rstride + nk);
            cp16(sB0 + so, Bp + nk); cp16(sB1 + so, Bp + rstride + nk);
            cp_commit();
            cp_wait<1>();
        } else {
            cp_wait<0>();
        }
        __syncthreads();

        const __nv_bfloat16* as = As[stage];
        const __nv_bfloat16* bs = Bs[stage];
#pragma unroll
        for (int kk = 0; kk < 32; kk += 16) {
            wmma::fragment<wmma::matrix_a, 16, 16, 16, __nv_bfloat16, wmma::row_major> af[2];
#pragma unroll
            for (int mi = 0; mi < 2; mi++)
                wmma::load_matrix_sync(af[mi], as + (wm * 32 + mi * 16) * SLD + kk, SLD);
#pragma unroll
            for (int ni = 0; ni < 4; ni++) {
                wmma::fragment<wmma::matrix_b, 16, 16, 16, __nv_bfloat16, wmma::col_major> bf;
                wmma::load_matrix_sync(bf, bs + (wn * 64 + ni * 16) * SLD + kk, SLD);
                wmma::mma_sync(acc[0][ni], af[0], bf, acc[0][ni]);
                wmma::mma_sync(acc[1][ni], af[1], bf, acc[1][ni]);
            }
        }
        __syncthreads();
    }

    // epilogue: reuse As as per-warp float staging (8 warps x 256 floats)
    const float* __restrict__ sq = (which == 0) ? g_sqd : g_sql;
    float* __restrict__ D = (which == 0) ? g_ddist : g_ldist;
    float* sc = (float*)As;
    float lmax = 0.f;
#pragma unroll
    for (int mi = 0; mi < 2; mi++) {
#pragma unroll
        for (int ni = 0; ni < 4; ni++) {
            wmma::store_matrix_sync(sc + wid * 256, acc[mi][ni], 16, wmma::mem_row_major);
            __syncwarp();
            int m0 = bi * 128 + wm * 32 + mi * 16;
            int n0 = bj * 128 + wn * 64 + ni * 16;
            int r = lane >> 1;
            int c0 = (lane & 1) << 3;
            float sqa = sq[m0 + r];
#pragma unroll
            for (int t = 0; t < 8; t++) {
                int cc = c0 + t;
                float g = sc[wid * 256 + r * 16 + cc];
                int gi = m0 + r, gj = n0 + cc;
                float d2 = sqa + sq[gj] - 2.0f * g;
                float d = (d2 > 0.f) ? sqrtf(d2) : 0.f;
                D[(size_t)gi * NPTS + gj] = d;
                if (bi != bj) D[(size_t)gj * NPTS + gi] = d;
                lmax = fmaxf(lmax, d);
            }
            __syncwarp();
        }
    }

    if (which == 0) {
#pragma unroll
        for (int off = 16; off; off >>= 1)
            lmax = fmaxf(lmax, __shfl_down_sync(0xffffffffu, lmax, off));
        __shared__ float smax[8];
        if (lane == 0) smax[wid] = lmax;
        __syncthreads();
        if (tid == 0) {
            float m = smax[0];
#pragma unroll
            for (int w = 1; w < 8; w++) m = fmaxf(m, smax[w]);
            atomicMax(&g_dmax_bits, __float_as_uint(m));
        }
    }
}

// ---- Boruvka scan: per-node min outgoing edge (one warp per row) ----
__global__ void __launch_bounds__(256) boruvka_scan() {
    int m = blockIdx.y;
    if (g_done[m]) return;
    const float* __restrict__ dist = (m == 0) ? g_ddist : g_ldist;
    const int* __restrict__ comp = g_comp[m];

    __shared__ __align__(16) int scomp[NPTS];
    for (int t = threadIdx.x; t < NPTS; t += 256) scomp[t] = comp[t];
    __syncthreads();

    int w = threadIdx.x >> 5, lane = threadIdx.x & 31;
    int row = blockIdx.x * 8 + w;
    int mycomp = scomp[row];
    const float4* __restrict__ rp = (const float4*)(dist + (size_t)row * NPTS);
    const int4* __restrict__ cp = (const int4*)scomp;

    unsigned bestv = 0xFFFFFFFFu;
    int bestj = 0;
#pragma unroll 8
    for (int k = 0; k < 32; k++) {
        int c4 = k * 32 + lane;
        float4 v = rp[c4];
        int4 cc = cp[c4];
        int col = c4 << 2;
        unsigned b;
        b = __float_as_uint(v.x); if (cc.x != mycomp && b < bestv) { bestv = b; bestj = col; }
        b = __float_as_uint(v.y); if (cc.y != mycomp && b < bestv) { bestv = b; bestj = col + 1; }
        b = __float_as_uint(v.z); if (cc.z != mycomp && b < bestv) { bestv = b; bestj = col + 2; }
        b = __float_as_uint(v.w); if (cc.w != mycomp && b < bestv) { bestv = b; bestj = col + 3; }
    }
    unsigned rv = __reduce_min_sync(0xffffffffu, bestv);
    unsigned rj = __reduce_min_sync(0xffffffffu,
                                    (bestv == rv) ? (unsigned)bestj : 0xFFFFFFFFu);
    if (lane == 0)
        g_nbest[m][row] = ((unsigned long long)rv << 24)
                        | ((unsigned long long)row << 12)
                        | (unsigned long long)rj;
}

// ---- Boruvka merge: per-comp best, hook, pointer-jump, relabel ----
__global__ void __launch_bounds__(1024) boruvka_merge() {
    int m = blockIdx.x;
    if (g_done[m]) return;
    __shared__ __align__(8) unsigned long long table[NPTS];
    __shared__ int scnt;
    int tid = threadIdx.x;
    int* __restrict__ parent = g_parent[m];
    const int* __restrict__ comp = g_comp[m];

    for (int c = tid; c < NPTS; c += 1024) { table[c] = ~0ull; parent[c] = c; }
    if (tid == 0) scnt = 0;
    __syncthreads();

    for (int n = tid; n < NPTS; n += 1024)
        atomicMin(&table[comp[n]], g_nbest[m][n]);
    __syncthreads();

    for (int c = tid; c < NPTS; c += 1024) {
        unsigned long long e = table[c];
        if (e != ~0ull) {
            int i = (int)((e >> 12) & 0xFFF);
            int j = (int)(e & 0xFFF);
            int t = comp[j];
            unsigned long long et = table[t];
            int i2 = (int)((et >> 12) & 0xFFF);
            int j2 = (int)(et & 0xFFF);
            bool mutual = (i2 == j) && (j2 == i);
            if (!mutual || c < t) {
                int pos = atomicAdd(&g_ecnt[m], 1);
                g_edges[m][2 * pos]     = i;
                g_edges[m][2 * pos + 1] = j;
            }
            parent[c] = (mutual && c < t) ? c : t;
        }
    }
    __syncthreads();

    for (int it = 0; it < 12; it++) {
        for (int c = tid; c < NPTS; c += 1024) {
            int p = parent[c];
            parent[c] = parent[p];
        }
        __syncthreads();
    }

    int* mark = (int*)table;
    for (int c = tid; c < NPTS; c += 1024) mark[c] = 0;
    __syncthreads();
    for (int n = tid; n < NPTS; n += 1024) {
        int r = parent[comp[n]];
        g_comp[m][n] = r;
        mark[r] = 1;
    }
    __syncthreads();
    int cnt = 0;
    for (int c = tid; c < NPTS; c += 1024) cnt += mark[c];
#pragma unroll
    for (int off = 16; off; off >>= 1) cnt += __shfl_down_sync(0xffffffffu, cnt, off);
    if ((tid & 31) == 0) atomicAdd(&scnt, cnt);
    __syncthreads();
    if (tid == 0 && scnt == 1) g_done[m] = 1;
}

// ---- gather MST edges, compute topo loss ----
__global__ void __launch_bounds__(1024) topo_kernel(const float* __restrict__ lnorm) {
    int tid = threadIdx.x;
    float invmax = 1.0f / __uint_as_float(g_dmax_bits);
    float invln = 1.0f / lnorm[0];
    float sd = 0.f, sl = 0.f;
    for (int e = tid; e < NEDGE; e += 1024) {
        int u = g_edges[0][2 * e], v = g_edges[0][2 * e + 1];
        size_t o = (size_t)u * NPTS + v;
        float t = g_ddist[o] * invmax - g_ldist[o] * invln;
        sd += t * t;
        u = g_edges[1][2 * e]; v = g_edges[1][2 * e + 1];
        o = (size_t)u * NPTS + v;
        t = g_ddist[o] * invmax - g_ldist[o] * invln;
        sl += t * t;
    }
#pragma unroll
    for (int off = 16; off; off >>= 1) {
        sd += __shfl_down_sync(0xffffffffu, sd, off);
        sl += __shfl_down_sync(0xffffffffu, sl, off);
    }
    __shared__ float ssd[32], ssl[32];
    if ((tid & 31) == 0) { ssd[tid >> 5] = sd; ssl[tid >> 5] = sl; }
    __syncthreads();
    if (tid < 32) {
        sd = ssd[tid]; sl = ssl[tid];
#pragma unroll
        for (int off = 16; off; off >>= 1) {
            sd += __shfl_down_sync(0xffffffffu, sd, off);
            sl += __shfl_down_sync(0xffffffffu, sl, off);
        }
        if (tid == 0) g_topo = (sd + sl) * (1.0f / NEDGE);
    }
}

__global__ void final_kernel(float* __restrict__ out) {
    int i = blockIdx.x * blockDim.x + threadIdx.x;
    if (i < NPTS) out[i] = g_ae[i] + 0.5f * g_topo;
}

extern "C" void kernel_launch(void* const* d_in, const int* in_sizes, int n_in,
                              void* d_out, int out_size) {
    const float* y_true      = (const float*)d_in[0];
    const float* latent      = (const float*)d_in[1];
    const float* y_pred      = (const float*)d_in[2];
    const float* latent_norm = (const float*)d_in[3];
    float* out = (float*)d_out;

    init_kernel<<<16, 256>>>();
    ae_sq_kernel<<<NPTS, 256>>>(y_true, y_pred);
    sq_lat_kernel<<<NPTS, 32>>>(latent);
    split_kernel<DDATA, 8><<<(NPTS * (DDATA / 4)) / 256, 256>>>(y_true, g_a16, g_b16);
    split_kernel<DLAT, 4><<<(NPTS * (DLAT / 4)) / 256, 256>>>(latent, g_al16, g_bl16);
    dim3 grid(32, 32);
    gram16_kernel<3 * DDATA><<<grid, 256>>>(g_a16, g_b16, 0);
    gram16_kernel<3 * DLAT><<<grid, 256>>>(g_al16, g_bl16, 1);
    for (int r = 0; r < ROUNDS; r++) {
        boruvka_scan<<<dim3(512, 2), 256>>>();
        boruvka_merge<<<2, 1024>>>();
    }
    topo_kernel<<<1, 1024>>>(latent_norm);
    final_kernel<<<16, 256>>>(out);
}

// round 7
// speedup vs baseline: 14.2869x; 14.2869x over previous
#include <cuda_runtime.h>
#include <cuda_bf16.h>
#include <math_constants.h>

#define NPTS 4096
#define DDATA 1024
#define DLAT 64
#define NEDGE (NPTS - 1)
#define ROUNDS 12

// ---- scratch (no allocations allowed: device globals) ----
static __device__ __nv_bfloat16 g_ddist[(size_t)NPTS * NPTS];  // raw data dist, bf16
static __device__ __nv_bfloat16 g_ldist[(size_t)NPTS * NPTS];  // raw latent dist, bf16
static __device__ float g_sqd[NPTS];
static __device__ float g_sql[NPTS];
static __device__ float g_ae[NPTS];
static __device__ int   g_edges[2][NEDGE * 2];
static __device__ int   g_ecnt[2];
static __device__ int   g_done[2];
static __device__ int   g_comp[2][NPTS];
static __device__ int   g_parent[2][NPTS];
static __device__ unsigned long long g_nbest[2][NPTS];
static __device__ float g_terms[2][NEDGE];
static __device__ unsigned g_dmax_bits;
static __device__ float g_topo;

__global__ void init_kernel() {
    int i = blockIdx.x * blockDim.x + threadIdx.x;
    if (i < NPTS) { g_comp[0][i] = i; g_comp[1][i] = i; }
    if (i == 0) {
        g_dmax_bits = 0u;
        g_ecnt[0] = 0; g_ecnt[1] = 0;
        g_done[0] = 0; g_done[1] = 0;
    }
}

// ---- AE loss + squared norms of y_true (one block per row) ----
__global__ void __launch_bounds__(256) ae_sq_kernel(
    const float* __restrict__ yt, const float* __restrict__ yp) {
    int row = blockIdx.x, tid = threadIdx.x;
    float4 a = ((const float4*)(yt + (size_t)row * DDATA))[tid];
    float4 b = ((const float4*)(yp + (size_t)row * DDATA))[tid];
    float dx = a.x - b.x, dy = a.y - b.y, dz = a.z - b.z, dw = a.w - b.w;
    float ae = dx * dx + dy * dy + dz * dz + dw * dw;
    float sq = a.x * a.x + a.y * a.y + a.z * a.z + a.w * a.w;
#pragma unroll
    for (int off = 16; off; off >>= 1) {
        ae += __shfl_down_sync(0xffffffffu, ae, off);
        sq += __shfl_down_sync(0xffffffffu, sq, off);
    }
    __shared__ float sae[8], ssq[8];
    if ((tid & 31) == 0) { sae[tid >> 5] = ae; ssq[tid >> 5] = sq; }
    __syncthreads();
    if (tid < 8) {
        ae = sae[tid]; sq = ssq[tid];
#pragma unroll
        for (int off = 4; off; off >>= 1) {
            ae += __shfl_down_sync(0xffu, ae, off);
            sq += __shfl_down_sync(0xffu, sq, off);
        }
        if (tid == 0) { g_ae[row] = ae * (1.0f / DDATA); g_sqd[row] = sq; }
    }
}

// ---- squared norms of latent rows (one warp per row) ----
__global__ void __launch_bounds__(32) sq_lat_kernel(const float* __restrict__ lat) {
    int row = blockIdx.x, tid = threadIdx.x;
    float2 v = ((const float2*)(lat + (size_t)row * DLAT))[tid];
    float s = v.x * v.x + v.y * v.y;
#pragma unroll
    for (int off = 16; off; off >>= 1) s += __shfl_down_sync(0xffffffffu, s, off);
    if (tid == 0) g_sql[row] = s;
}

// ---- packed fp32x2 helpers (Blackwell FFMA2, PTX-only) ----
__device__ __forceinline__ unsigned long long bcast2(float x) {
    unsigned long long r;
    asm("mov.b64 %0, {%1, %1};" : "=l"(r) : "r"(__float_as_uint(x)));
    return r;
}
__device__ __forceinline__ void ffma2(unsigned long long& d,
                                      unsigned long long a, unsigned long long b) {
    asm("fma.rn.f32x2 %0, %1, %2, %0;" : "+l"(d) : "l"(a), "l"(b));
}

// ---- fused gram -> Euclidean distance matrices (bf16 out) ----
// grid (33, 32): bx<32 & by<=bx -> data tile (by,bx); bx<32 & by>bx -> latent
// tile (bx,by); bx==32 -> latent diagonal tile (by,by). 128x128 tile, 256 thr,
// 8x8 per thread via packed f32x2 FMA (m-pairs), BK=8.
__global__ void __launch_bounds__(256) gram_kernel(
    const float* __restrict__ Yd, const float* __restrict__ Yl) {
    int bx = blockIdx.x, by = blockIdx.y;
    int bi, bj, which;
    if (bx < 32) {
        if (by <= bx) { which = 0; bi = by; bj = bx; }
        else          { which = 1; bi = bx; bj = by; }
    } else            { which = 1; bi = by; bj = by; }
    const float* __restrict__ X  = which ? Yl : Yd;
    const int K = which ? DLAT : DDATA;
    const float* __restrict__ sq = which ? g_sql : g_sqd;
    __nv_bfloat16* __restrict__ D = which ? g_ldist : g_ddist;

    __shared__ float As[8][128], Bs[8][128];
    int tid = threadIdx.x;
    int tx = tid & 15, ty = tid >> 4;

    unsigned long long acc2[4][8];
#pragma unroll
    for (int mp = 0; mp < 4; mp++)
#pragma unroll
        for (int n = 0; n < 8; n++) acc2[mp][n] = 0ull;

    int lr = tid >> 1;
    int lk = (tid & 1) << 2;
    const float* Ap = X + (size_t)(bi * 128 + lr) * K + lk;
    const float* Bp = X + (size_t)(bj * 128 + lr) * K + lk;

    for (int k0 = 0; k0 < K; k0 += 8) {
        float4 a = *(const float4*)(Ap + k0);
        float4 b = *(const float4*)(Bp + k0);
        __syncthreads();
        As[lk + 0][lr] = a.x; As[lk + 1][lr] = a.y;
        As[lk + 2][lr] = a.z; As[lk + 3][lr] = a.w;
        Bs[lk + 0][lr] = b.x; Bs[lk + 1][lr] = b.y;
        Bs[lk + 2][lr] = b.z; Bs[lk + 3][lr] = b.w;
        __syncthreads();
#pragma unroll
        for (int kk = 0; kk < 8; kk++) {
            const unsigned long long* ap =
                (const unsigned long long*)&As[kk][ty * 8];
            unsigned long long a20 = ap[0], a21 = ap[1], a22 = ap[2], a23 = ap[3];
            float br[8];
            *(float4*)(br)     = *(const float4*)(&Bs[kk][tx * 8]);
            *(float4*)(br + 4) = *(const float4*)(&Bs[kk][tx * 8 + 4]);
#pragma unroll
            for (int n = 0; n < 8; n++) {
                unsigned long long bb = bcast2(br[n]);
                ffma2(acc2[0][n], a20, bb);
                ffma2(acc2[1][n], a21, bb);
                ffma2(acc2[2][n], a22, bb);
                ffma2(acc2[3][n], a23, bb);
            }
        }
    }

    // epilogue: d = sqrt(max(sq_i + sq_j - 2g, 0)), store bf16 both halves
    float sqa[8], sqb[8];
#pragma unroll
    for (int m = 0; m < 8; m++) sqa[m] = sq[bi * 128 + ty * 8 + m];
#pragma unroll
    for (int n = 0; n < 8; n++) sqb[n] = sq[bj * 128 + tx * 8 + n];

    float dmat[8][8];
    float lmax = 0.f;
#pragma unroll
    for (int mp = 0; mp < 4; mp++)
#pragma unroll
        for (int n = 0; n < 8; n++) {
            float glo = __uint_as_float((unsigned)(acc2[mp][n] & 0xFFFFFFFFull));
            float ghi = __uint_as_float((unsigned)(acc2[mp][n] >> 32));
            float d2a = sqa[2 * mp] + sqb[n] - 2.0f * glo;
            float d2b = sqa[2 * mp + 1] + sqb[n] - 2.0f * ghi;
            float da = (d2a > 0.f) ? sqrtf(d2a) : 0.f;
            float db = (d2b > 0.f) ? sqrtf(d2b) : 0.f;
            dmat[2 * mp][n] = da; dmat[2 * mp + 1][n] = db;
            lmax = fmaxf(lmax, fmaxf(da, db));
        }

#pragma unroll
    for (int m = 0; m < 8; m++) {
        int gi = bi * 128 + ty * 8 + m;
        uint4 pk;
        ((__nv_bfloat162*)&pk)[0] = __floats2bfloat162_rn(dmat[m][0], dmat[m][1]);
        ((__nv_bfloat162*)&pk)[1] = __floats2bfloat162_rn(dmat[m][2], dmat[m][3]);
        ((__nv_bfloat162*)&pk)[2] = __floats2bfloat162_rn(dmat[m][4], dmat[m][5]);
        ((__nv_bfloat162*)&pk)[3] = __floats2bfloat162_rn(dmat[m][6], dmat[m][7]);
        *(uint4*)(D + (size_t)gi * NPTS + bj * 128 + tx * 8) = pk;
    }
    if (bi != bj) {
#pragma unroll
        for (int n = 0; n < 8; n++) {
            int gj = bj * 128 + tx * 8 + n;
            uint4 pk;
            ((__nv_bfloat162*)&pk)[0] = __floats2bfloat162_rn(dmat[0][n], dmat[1][n]);
            ((__nv_bfloat162*)&pk)[1] = __floats2bfloat162_rn(dmat[2][n], dmat[3][n]);
            ((__nv_bfloat162*)&pk)[2] = __floats2bfloat162_rn(dmat[4][n], dmat[5][n]);
            ((__nv_bfloat162*)&pk)[3] = __floats2bfloat162_rn(dmat[6][n], dmat[7][n]);
            *(uint4*)(D + (size_t)gj * NPTS + bi * 128 + ty * 8) = pk;
        }
    }

    if (which == 0) {
        int lane = tid & 31, wid = tid >> 5;
#pragma unroll
        for (int off = 16; off; off >>= 1)
            lmax = fmaxf(lmax, __shfl_down_sync(0xffffffffu, lmax, off));
        __shared__ float smax[8];
        if (lane == 0) smax[wid] = lmax;
        __syncthreads();
        if (tid == 0) {
            float mx = smax[0];
#pragma unroll
            for (int w = 1; w < 8; w++) mx = fmaxf(mx, smax[w]);
            atomicMax(&g_dmax_bits, __float_as_uint(mx));
        }
    }
}

// ---- Boruvka scan over bf16 matrix: per-node min outgoing edge ----
// grid (512, 2): one warp per row, 8 rows per 256-thread block.
__global__ void __launch_bounds__(256) boruvka_scan() {
    int m = blockIdx.y;
    if (g_done[m]) return;
    const __nv_bfloat16* __restrict__ dist = (m == 0) ? g_ddist : g_ldist;
    const int* __restrict__ comp = g_comp[m];

    __shared__ __align__(16) unsigned short scomp[NPTS];
    for (int t = threadIdx.x; t < NPTS; t += 256)
        scomp[t] = (unsigned short)comp[t];
    __syncthreads();

    int w = threadIdx.x >> 5, lane = threadIdx.x & 31;
    int row = blockIdx.x * 8 + w;
    unsigned mycomp = scomp[row];
    const uint4* __restrict__ rp = (const uint4*)(dist + (size_t)row * NPTS);
    const uint4* __restrict__ cp = (const uint4*)scomp;

    unsigned bestv = 0xFFFFFFFFu;
    int bestj = 0;
#define PROC2(vw, cw, cbase)                                          \
    {                                                                  \
        unsigned h0 = (vw) & 0xFFFFu, h1 = (vw) >> 16;                 \
        unsigned c0 = (cw) & 0xFFFFu, c1 = (cw) >> 16;                 \
        if (c0 != mycomp && h0 < bestv) { bestv = h0; bestj = (cbase); }\
        if (c1 != mycomp && h1 < bestv) { bestv = h1; bestj = (cbase) + 1; }\
    }
#pragma unroll 4
    for (int k = 0; k < 16; k++) {
        int c8 = k * 32 + lane;
        uint4 v = rp[c8];
        uint4 cc = cp[c8];
        int col = c8 << 3;
        PROC2(v.x, cc.x, col);
        PROC2(v.y, cc.y, col + 2);
        PROC2(v.z, cc.z, col + 4);
        PROC2(v.w, cc.w, col + 6);
    }
#undef PROC2
    unsigned rv = __reduce_min_sync(0xffffffffu, bestv);
    unsigned rj = __reduce_min_sync(0xffffffffu,
                                    (bestv == rv) ? (unsigned)bestj : 0xFFFFFFFFu);
    if (lane == 0)
        g_nbest[m][row] = ((unsigned long long)rv << 24)
                        | ((unsigned long long)row << 12)
                        | (unsigned long long)rj;
}

// ---- Boruvka merge: per-comp best, hook, pointer-jump, relabel ----
__global__ void __launch_bounds__(1024) boruvka_merge() {
    int m = blockIdx.x;
    if (g_done[m]) return;
    __shared__ __align__(8) unsigned long long table[NPTS];
    __shared__ int scnt;
    int tid = threadIdx.x;
    int* __restrict__ parent = g_parent[m];
    const int* __restrict__ comp = g_comp[m];

    for (int c = tid; c < NPTS; c += 1024) { table[c] = ~0ull; parent[c] = c; }
    if (tid == 0) scnt = 0;
    __syncthreads();

    for (int n = tid; n < NPTS; n += 1024)
        atomicMin(&table[comp[n]], g_nbest[m][n]);
    __syncthreads();

    for (int c = tid; c < NPTS; c += 1024) {
        unsigned long long e = table[c];
        if (e != ~0ull) {
            int i = (int)((e >> 12) & 0xFFF);
            int j = (int)(e & 0xFFF);
            int t = comp[j];
            unsigned long long et = table[t];
            int i2 = (int)((et >> 12) & 0xFFF);
            int j2 = (int)(et & 0xFFF);
            bool mutual = (i2 == j) && (j2 == i);
            if (!mutual || c < t) {
                int pos = atomicAdd(&g_ecnt[m], 1);
                g_edges[m][2 * pos]     = i;
                g_edges[m][2 * pos + 1] = j;
            }
            parent[c] = (mutual && c < t) ? c : t;
        }
    }
    __syncthreads();

    for (int it = 0; it < 12; it++) {
        for (int c = tid; c < NPTS; c += 1024) {
            int p = parent[c];
            parent[c] = parent[p];
        }
        __syncthreads();
    }

    int* mark = (int*)table;
    for (int c = tid; c < NPTS; c += 1024) mark[c] = 0;
    __syncthreads();
    for (int n = tid; n < NPTS; n += 1024) {
        int r = parent[comp[n]];
        g_comp[m][n] = r;
        mark[r] = 1;
    }
    __syncthreads();
    int cnt = 0;
    for (int c = tid; c < NPTS; c += 1024) cnt += mark[c];
#pragma unroll
    for (int off = 16; off; off >>= 1) cnt += __shfl_down_sync(0xffffffffu, cnt, off);
    if ((tid & 31) == 0) atomicAdd(&scnt, cnt);
    __syncthreads();
    if (tid == 0 && scnt == 1) g_done[m] = 1;
}

// ---- gather: recompute exact fp32 distances per MST edge (1 warp/edge) ----
__global__ void __launch_bounds__(256) topo_kernel(
    const float* __restrict__ yt, const float* __restrict__ lat,
    const float* __restrict__ lnorm) {
    int gw = blockIdx.x * 8 + (threadIdx.x >> 5);
    int lane = threadIdx.x & 31;
    int m = gw & 1, e = gw >> 1;
    if (e >= NEDGE) return;
    int u = g_edges[m][2 * e], v = g_edges[m][2 * e + 1];
    const float4* au = (const float4*)(yt + (size_t)u * DDATA);
    const float4* av = (const float4*)(yt + (size_t)v * DDATA);
    float dot = 0.f;
#pragma unroll
    for (int i = 0; i < 8; i++) {
        float4 a = au[lane + i * 32], b = av[lane + i * 32];
        dot += a.x * b.x + a.y * b.y + a.z * b.z + a.w * b.w;
    }
    float dl = 0.f;
    if (lane < 16) {
        float4 a = ((const float4*)(lat + (size_t)u * DLAT))[lane];
        float4 b = ((const float4*)(lat + (size_t)v * DLAT))[lane];
        dl = a.x * b.x + a.y * b.y + a.z * b.z + a.w * b.w;
    }
#pragma unroll
    for (int off = 16; off; off >>= 1) {
        dot += __shfl_down_sync(0xffffffffu, dot, off);
        dl  += __shfl_down_sync(0xffffffffu, dl, off);
    }
    if (lane == 0) {
        float dd2 = g_sqd[u] + g_sqd[v] - 2.0f * dot;
        float dd = (dd2 > 0.f) ? sqrtf(dd2) : 0.f;
        float dl2 = g_sql[u] + g_sql[v] - 2.0f * dl;
        float dlat = (dl2 > 0.f) ? sqrtf(dl2) : 0.f;
        float invmax = 1.0f / __uint_as_float(g_dmax_bits);
        float t = dd * invmax - dlat / lnorm[0];
        g_terms[m][e] = t * t;
    }
}

// ---- deterministic fixed-order reduction of edge terms ----
__global__ void __launch_bounds__(1024) reduce_kernel() {
    int tid = threadIdx.x;
    float s = 0.f;
    for (int e = tid; e < NEDGE; e += 1024) s += g_terms[0][e] + g_terms[1][e];
#pragma unroll
    for (int off = 16; off; off >>= 1) s += __shfl_down_sync(0xffffffffu, s, off);
    __shared__ float ss[32];
    if ((tid & 31) == 0) ss[tid >> 5] = s;
    __syncthreads();
    if (tid < 32) {
        s = ss[tid];
#pragma unroll
        for (int off = 16; off; off >>= 1) s += __shfl_down_sync(0xffffffffu, s, off);
        if (tid == 0) g_topo = s * (1.0f / NEDGE);
    }
}

__global__ void final_kernel(float* __restrict__ out) {
    int i = blockIdx.x * blockDim.x + threadIdx.x;
    if (i < NPTS) out[i] = g_ae[i] + 0.5f * g_topo;
}

extern "C" void kernel_launch(void* const* d_in, const int* in_sizes, int n_in,
                              void* d_out, int out_size) {
    const float* y_true      = (const float*)d_in[0];
    const float* latent      = (const float*)d_in[1];
    const float* y_pred      = (const float*)d_in[2];
    const float* latent_norm = (const float*)d_in[3];
    float* out = (float*)d_out;

    init_kernel<<<16, 256>>>();
    ae_sq_kernel<<<NPTS, 256>>>(y_true, y_pred);
    sq_lat_kernel<<<NPTS, 32>>>(latent);
    gram_kernel<<<dim3(33, 32), 256>>>(y_true, latent);
    for (int r = 0; r < ROUNDS; r++) {
        boruvka_scan<<<dim3(512, 2), 256>>>();
        boruvka_merge<<<2, 1024>>>();
    }
    topo_kernel<<<1024, 256>>>(y_true, latent, latent_norm);
    reduce_kernel<<<1, 1024>>>();
    final_kernel<<<16, 256>>>(out);
}